// round 3
// baseline (speedup 1.0000x reference)
#include <cuda_runtime.h>
#include <math.h>

// ---------------------------------------------------------------------------
// LCNECortexLSTM  —  B=65536, D=H=256, fp32
//
// Stage graph (launch order):
//   G1  : x_in = X@Wx+bx ; LC_raw = x_in + prev_LC@Wh + bh        (dual-K GEMM)
//   G2  : forget = sigmoid(prev_Cortex@Wf + bf)
//   R1  : column stats(LC_raw) -> scale/shift (BN1, g1/be1)
//   E1  : LC_t = leaky(bn1(LC_raw))            -> out[0]
//   G3  : NE_raw = LC_t@WLC + bLC              -> g_raw
//   R2/E2: NE_t = leaky(bn2(NE_raw))           -> out[1]
//   G4  : nc  = x_in@WC + bC + forget*cell     -> out[4]  (new_cell partial)
//   G5  : ne2 = NE_t@WLC + bLC                 -> g_raw
//   G6  : nc += sigmoid(x_in@Wi + bi)*0.1*ne2  -> out[4]  (new_cell final)
//   R3/E3: C_t = leaky(bn3(new_cell))          -> out[2]
//   P   : p[i] = (LC_t+NE_t+C_t)[i,:] . WP
//   G7  : Pupil = sigmoid(C_t@Wo + bo) * (p + bP)  -> out[3]
// ---------------------------------------------------------------------------

#define B_DIM 65536
#define H_DIM 256
#define BH_ELEMS (B_DIM * H_DIM)      // 16,777,216

#define BM 128
#define BN 128
#define BK 16
#define TM 8
#define TN 8

#define NCHUNK 1024
#define ROWS_PER_CHUNK (B_DIM / NCHUNK)   // 64
#define BN_EPS_F 1e-5f
#define LAMBDA_C 0.1f

// ------------------------------ scratch (global, no allocs) ----------------
__device__ float g_xin[BH_ELEMS];                 // x_input
__device__ float g_raw[BH_ELEMS];                 // LC_raw / NE_raw / ne2 (reused)
__device__ float g_forget[BH_ELEMS];              // forget gate
__device__ float g_p[B_DIM];                      // pupil pre-activation [B]
__device__ float g_part[2 * H_DIM * NCHUNK];      // column partial sums / sumsq
__device__ float g_scale[H_DIM];                  // BN fused scale
__device__ float g_shift[H_DIM];                  // BN fused shift

__device__ __forceinline__ float sigmoidf_(float x) { return 1.0f / (1.0f + expf(-x)); }
__device__ __forceinline__ float leakyf_(float x)   { return x > 0.0f ? x : 0.1f * x; }

// ------------------------------ GEMM core ----------------------------------
// acc += A[rowBase:+128, 0:256] @ W[0:256, colBase:+128]
// A: [*,256] row-major, W: [256,256] row-major. 256 threads, 8x8 per thread.
// Thread (tx,ty): rows rowBase+ty*8+i; cols colBase + {tx*4+q, 64+tx*4+q}.
__device__ __forceinline__ void mm256(const float* __restrict__ A,
                                      const float* __restrict__ W,
                                      int rowBase, int colBase,
                                      float (&acc)[TM][TN],
                                      float* sA, float* sW)
{
    const int tid = threadIdx.x;
    const int tx = tid & 15, ty = tid >> 4;
    for (int kt = 0; kt < 256; kt += BK) {
        // A tile [128 x 16] -> sA transposed as [16][128]
        #pragma unroll
        for (int l = 0; l < 2; ++l) {
            int fi = tid + l * 256;            // 0..511 float4 slots
            int r  = fi >> 2;                  // 0..127
            int c4 = fi & 3;                   // 0..3
            float4 v = *(const float4*)(A + (size_t)(rowBase + r) * H_DIM + kt + c4 * 4);
            sA[(c4 * 4 + 0) * BM + r] = v.x;
            sA[(c4 * 4 + 1) * BM + r] = v.y;
            sA[(c4 * 4 + 2) * BM + r] = v.z;
            sA[(c4 * 4 + 3) * BM + r] = v.w;
        }
        // W tile [16 x 128] -> sW row-major
        #pragma unroll
        for (int l = 0; l < 2; ++l) {
            int fi = tid + l * 256;
            int r  = fi >> 5;                  // 0..15
            int c4 = fi & 31;                  // 0..31
            *(float4*)(sW + r * BN + c4 * 4) =
                *(const float4*)(W + (size_t)(kt + r) * H_DIM + colBase + c4 * 4);
        }
        __syncthreads();
        #pragma unroll
        for (int k = 0; k < BK; ++k) {
            float ra[TM], rb[TN];
            *(float4*)(ra)     = *(const float4*)(sA + k * BM + ty * TM);
            *(float4*)(ra + 4) = *(const float4*)(sA + k * BM + ty * TM + 4);
            *(float4*)(rb)     = *(const float4*)(sW + k * BN + tx * 4);
            *(float4*)(rb + 4) = *(const float4*)(sW + k * BN + 64 + tx * 4);
            #pragma unroll
            for (int i = 0; i < TM; ++i)
                #pragma unroll
                for (int j = 0; j < TN; ++j)
                    acc[i][j] += ra[i] * rb[j];
        }
        __syncthreads();
    }
}

// Column index of acc[i][jj*4+q] relative to colBase:  jj*64 + tx*4 + q
#define EPI_BEGIN()                                                         \
    const int tx = threadIdx.x & 15, ty = threadIdx.x >> 4;                 \
    _Pragma("unroll")                                                       \
    for (int i = 0; i < TM; ++i) {                                          \
        const int row = rowBase + ty * TM + i;                              \
        const size_t ro = (size_t)row * H_DIM;                              \
        _Pragma("unroll")                                                   \
        for (int jj = 0; jj < 2; ++jj) {                                    \
            const int cb = colBase + jj * 64 + tx * 4;                      \
            float t[4];                                                     \
            _Pragma("unroll")                                               \
            for (int q = 0; q < 4; ++q) {                                   \
                const float a = acc[i][jj * 4 + q];                         \
                const int col = cb + q;                                     \
                (void)col;

#define EPI_END(dst)                                                        \
            }                                                               \
            *(float4*)((dst) + ro + cb) = *(float4*)t;                      \
        }                                                                   \
    }

// ------------------------------ GEMM kernels -------------------------------

// G1: x_in = X@Wx+bx (-> g_xin); LC_raw = x_in + prev_LC@Wh + bh (-> g_raw)
__global__ __launch_bounds__(256) void k_gemm_s1(
    const float* __restrict__ X,  const float* __restrict__ Wx, const float* __restrict__ bx,
    const float* __restrict__ pLC, const float* __restrict__ Wh, const float* __restrict__ bh)
{
    __shared__ __align__(16) float sA[BK * BM];
    __shared__ __align__(16) float sW[BK * BN];
    const int rowBase = blockIdx.y * BM, colBase = blockIdx.x * BN;
    float acc[TM][TN] = {};
    mm256(X, Wx, rowBase, colBase, acc, sA, sW);
    {
        EPI_BEGIN()
            t[q] = a + bx[col];
        EPI_END(g_xin)
    }
    mm256(pLC, Wh, rowBase, colBase, acc, sA, sW);
    {
        EPI_BEGIN()
            t[q] = a + bx[col] + bh[col];
        EPI_END(g_raw)
    }
}

// G2: forget = sigmoid(prev_Cortex@Wf + bf) -> g_forget
__global__ __launch_bounds__(256) void k_gemm_forget(
    const float* __restrict__ pC, const float* __restrict__ Wf, const float* __restrict__ bf)
{
    __shared__ __align__(16) float sA[BK * BM];
    __shared__ __align__(16) float sW[BK * BN];
    const int rowBase = blockIdx.y * BM, colBase = blockIdx.x * BN;
    float acc[TM][TN] = {};
    mm256(pC, Wf, rowBase, colBase, acc, sA, sW);
    EPI_BEGIN()
        t[q] = sigmoidf_(a + bf[col]);
    EPI_END(g_forget)
}

// G3/G5: g_raw = A@WLC + bLC   (A = LC_t or NE_t)
__global__ __launch_bounds__(256) void k_gemm_ne(
    const float* __restrict__ Amat, const float* __restrict__ W, const float* __restrict__ bvec)
{
    __shared__ __align__(16) float sA[BK * BM];
    __shared__ __align__(16) float sW[BK * BN];
    const int rowBase = blockIdx.y * BM, colBase = blockIdx.x * BN;
    float acc[TM][TN] = {};
    mm256(Amat, W, rowBase, colBase, acc, sA, sW);
    EPI_BEGIN()
        t[q] = a + bvec[col];
    EPI_END(g_raw)
}

// G4: newcell_partial = x_in@WC + bC + forget*cell  -> NC (d_out region 4)
__global__ __launch_bounds__(256) void k_gemm_cell_a(
    const float* __restrict__ WC, const float* __restrict__ bC,
    const float* __restrict__ cell, float* __restrict__ NC)
{
    __shared__ __align__(16) float sA[BK * BM];
    __shared__ __align__(16) float sW[BK * BN];
    const int rowBase = blockIdx.y * BM, colBase = blockIdx.x * BN;
    float acc[TM][TN] = {};
    mm256(g_xin, WC, rowBase, colBase, acc, sA, sW);
    EPI_BEGIN()
        if (q == 0) {}  // keep structure
        {
            float fg[4], cs[4];
            if (q == 0) {
                *(float4*)fg = *(const float4*)(g_forget + ro + cb);
                *(float4*)cs = *(const float4*)(cell + ro + cb);
                t[0] = a + bC[col] + fg[0] * cs[0];
                t[1] = acc[i][jj * 4 + 1] + bC[cb + 1] + fg[1] * cs[1];
                t[2] = acc[i][jj * 4 + 2] + bC[cb + 2] + fg[2] * cs[2];
                t[3] = acc[i][jj * 4 + 3] + bC[cb + 3] + fg[3] * cs[3];
            }
        }
    EPI_END(NC)
}

// G6: NC += sigmoid(x_in@Wi + bi) * 0.1 * ne2(g_raw)  -> NC final new_cell
__global__ __launch_bounds__(256) void k_gemm_ig(
    const float* __restrict__ Wi, const float* __restrict__ bi, float* __restrict__ NC)
{
    __shared__ __align__(16) float sA[BK * BM];
    __shared__ __align__(16) float sW[BK * BN];
    const int rowBase = blockIdx.y * BM, colBase = blockIdx.x * BN;
    float acc[TM][TN] = {};
    mm256(g_xin, Wi, rowBase, colBase, acc, sA, sW);
    EPI_BEGIN()
        {
            float ne2 = g_raw[ro + col];
            float nc  = NC[ro + col];
            t[q] = nc + sigmoidf_(a + bi[col]) * LAMBDA_C * ne2;
        }
    EPI_END(NC)
}

// G7: Pupil = sigmoid(C_t@Wo + bo) * (g_p[row] + bP[0])
__global__ __launch_bounds__(256) void k_gemm_pupil(
    const float* __restrict__ Ct, const float* __restrict__ Wo, const float* __restrict__ bo,
    const float* __restrict__ bP, float* __restrict__ Pup)
{
    __shared__ __align__(16) float sA[BK * BM];
    __shared__ __align__(16) float sW[BK * BN];
    const int rowBase = blockIdx.y * BM, colBase = blockIdx.x * BN;
    float acc[TM][TN] = {};
    mm256(Ct, Wo, rowBase, colBase, acc, sA, sW);
    const float pb = bP[0];
    EPI_BEGIN()
        {
            float pp = g_p[row] + pb;
            t[q] = sigmoidf_(a + bo[col]) * pp;
        }
    EPI_END(Pup)
}

// ------------------------------ BN reductions ------------------------------

// pass 1: per-(chunk,column) partial sum / sumsq.  x = ext (if use_ext) else g_raw
__global__ void k_colstat1(const float* __restrict__ ext, int use_ext)
{
    const float* x = use_ext ? ext : g_raw;
    const int col = threadIdx.x;      // 0..255
    const int ch  = blockIdx.x;       // 0..NCHUNK-1
    const float* p = x + (size_t)ch * ROWS_PER_CHUNK * H_DIM + col;
    float s = 0.0f, s2 = 0.0f;
    #pragma unroll 8
    for (int r = 0; r < ROWS_PER_CHUNK; ++r) {
        float v = p[(size_t)r * H_DIM];
        s += v; s2 += v * v;
    }
    g_part[col * NCHUNK + ch] = s;
    g_part[H_DIM * NCHUNK + col * NCHUNK + ch] = s2;
}

// pass 2: one block per column -> g_scale/g_shift (fused gamma/beta)
__global__ void k_colstat2(const float* __restrict__ gamma, const float* __restrict__ beta)
{
    const int b = blockIdx.x, t = threadIdx.x;
    float s = 0.0f, s2 = 0.0f;
    #pragma unroll
    for (int q = 0; q < NCHUNK / 256; ++q) {
        int ch = t * (NCHUNK / 256) + q;
        s  += g_part[b * NCHUNK + ch];
        s2 += g_part[H_DIM * NCHUNK + b * NCHUNK + ch];
    }
    __shared__ float rs[256], rq[256];
    rs[t] = s; rq[t] = s2;
    __syncthreads();
    for (int off = 128; off > 0; off >>= 1) {
        if (t < off) { rs[t] += rs[t + off]; rq[t] += rq[t + off]; }
        __syncthreads();
    }
    if (t == 0) {
        float mean = rs[0] * (1.0f / B_DIM);
        float var  = rq[0] * (1.0f / B_DIM) - mean * mean;
        float sc   = gamma[b] * rsqrtf(var + BN_EPS_F);
        g_scale[b] = sc;
        g_shift[b] = beta[b] - mean * sc;
    }
}

// elementwise: out = leaky(in*scale + shift)
__global__ void k_bnleaky(const float* __restrict__ ext, int use_ext, float* __restrict__ out)
{
    const float* in = use_ext ? ext : g_raw;
    size_t i = (size_t)blockIdx.x * blockDim.x + threadIdx.x;  // over BH/4
    int colb = (int)(i & 63) * 4;
    float4 v = ((const float4*)in)[i];
    float t[4] = {v.x, v.y, v.z, v.w};
    float o[4];
    #pragma unroll
    for (int q = 0; q < 4; ++q) {
        float y = t[q] * g_scale[colb + q] + g_shift[colb + q];
        o[q] = leakyf_(y);
    }
    ((float4*)out)[i] = *(float4*)o;
}

// pupil pre: g_p[row] = (LC_t + NE_t + C_t)[row,:] . WP
__global__ void k_pupil(const float* __restrict__ out_base, const float* __restrict__ WP)
{
    const int warp = threadIdx.x >> 5, lane = threadIdx.x & 31;
    const int row = blockIdx.x * 8 + warp;
    const size_t off = (size_t)row * H_DIM;
    const float* LC = out_base;
    const float* NE = out_base + (size_t)BH_ELEMS;
    const float* CT = out_base + 2 * (size_t)BH_ELEMS;
    float s = 0.0f;
    #pragma unroll
    for (int h = 0; h < 2; ++h) {
        int c = lane * 4 + h * 128;
        float4 a = *(const float4*)(LC + off + c);
        float4 b = *(const float4*)(NE + off + c);
        float4 d = *(const float4*)(CT + off + c);
        float4 w = *(const float4*)(WP + c);
        s += (a.x + b.x + d.x) * w.x + (a.y + b.y + d.y) * w.y
           + (a.z + b.z + d.z) * w.z + (a.w + b.w + d.w) * w.w;
    }
    #pragma unroll
    for (int o = 16; o > 0; o >>= 1) s += __shfl_xor_sync(0xffffffffu, s, o);
    if (lane == 0) g_p[row] = s;
}

// ------------------------------ launcher -----------------------------------
extern "C" void kernel_launch(void* const* d_in, const int* in_sizes, int n_in,
                              void* d_out, int out_size)
{
    (void)in_sizes; (void)n_in; (void)out_size;
    const float* X    = (const float*)d_in[0];
    const float* pLC  = (const float*)d_in[1];
    const float* pC   = (const float*)d_in[2];
    const float* cell = (const float*)d_in[3];
    const float* Wx   = (const float*)d_in[4];
    const float* bx   = (const float*)d_in[5];
    const float* Wh   = (const float*)d_in[6];
    const float* bh   = (const float*)d_in[7];
    const float* WLC  = (const float*)d_in[8];
    const float* bLC  = (const float*)d_in[9];
    const float* WC   = (const float*)d_in[10];
    const float* bC   = (const float*)d_in[11];
    const float* WP   = (const float*)d_in[12];
    const float* bP   = (const float*)d_in[13];
    const float* Wf   = (const float*)d_in[14];
    const float* bf   = (const float*)d_in[15];
    const float* Wi   = (const float*)d_in[16];
    const float* bi   = (const float*)d_in[17];
    const float* Wo   = (const float*)d_in[18];
    const float* bo   = (const float*)d_in[19];
    const float* g1   = (const float*)d_in[20];
    const float* be1  = (const float*)d_in[21];
    const float* g2   = (const float*)d_in[22];
    const float* be2  = (const float*)d_in[23];
    const float* g3   = (const float*)d_in[24];
    const float* be3  = (const float*)d_in[25];

    float* out  = (float*)d_out;
    float* LC_t = out;
    float* NE_t = out + (size_t)BH_ELEMS;
    float* C_t  = out + 2 * (size_t)BH_ELEMS;
    float* Pup  = out + 3 * (size_t)BH_ELEMS;
    float* NC   = out + 4 * (size_t)BH_ELEMS;

    dim3 gg(H_DIM / BN, B_DIM / BM);   // (2, 512)
    const int EW_GRID = BH_ELEMS / 4 / 256;  // 16384

    // Stage 1: x_in, LC_raw, forget
    k_gemm_s1<<<gg, 256>>>(X, Wx, bx, pLC, Wh, bh);
    k_gemm_forget<<<gg, 256>>>(pC, Wf, bf);

    // BN1 -> LC_t
    k_colstat1<<<NCHUNK, 256>>>(nullptr, 0);
    k_colstat2<<<H_DIM, 256>>>(g1, be1);
    k_bnleaky<<<EW_GRID, 256>>>(nullptr, 0, LC_t);

    // NE_raw -> BN2 -> NE_t
    k_gemm_ne<<<gg, 256>>>(LC_t, WLC, bLC);
    k_colstat1<<<NCHUNK, 256>>>(nullptr, 0);
    k_colstat2<<<H_DIM, 256>>>(g2, be2);
    k_bnleaky<<<EW_GRID, 256>>>(nullptr, 0, NE_t);

    // new_cell = forget*cell + x_in@WC+bC  + 0.1*ig*(NE_t@WLC+bLC)
    k_gemm_cell_a<<<gg, 256>>>(WC, bC, cell, NC);
    k_gemm_ne<<<gg, 256>>>(NE_t, WLC, bLC);       // ne2 -> g_raw
    k_gemm_ig<<<gg, 256>>>(Wi, bi, NC);

    // BN3 -> C_t
    k_colstat1<<<NCHUNK, 256>>>(NC, 1);
    k_colstat2<<<H_DIM, 256>>>(g3, be3);
    k_bnleaky<<<EW_GRID, 256>>>(NC, 1, C_t);

    // Pupil
    k_pupil<<<B_DIM / 8, 256>>>(out, WP);
    k_gemm_pupil<<<gg, 256>>>(C_t, Wo, bo, bP, Pup);
}

// round 5
// speedup vs baseline: 1.0034x; 1.0034x over previous
#include <cuda_runtime.h>
#include <math.h>

// ---------------------------------------------------------------------------
// LCNECortexLSTM  —  B=65536, D=H=256, fp32
//
// Stage graph (launch order):
//   G1  : x_in = X@Wx+bx ; LC_raw = x_in + prev_LC@Wh + bh        (dual-K GEMM)
//   G2  : forget = sigmoid(prev_Cortex@Wf + bf)
//   R1  : column stats(LC_raw) -> scale/shift (BN1, g1/be1)
//   E1  : LC_t = leaky(bn1(LC_raw))            -> out[0]
//   G3  : NE_raw = LC_t@WLC + bLC              -> g_raw
//   R2/E2: NE_t = leaky(bn2(NE_raw))           -> out[1]
//   G4  : nc  = x_in@WC + bC + forget*cell     -> out[4]  (new_cell partial)
//   G5  : ne2 = NE_t@WLC + bLC                 -> g_raw
//   G6  : nc += sigmoid(x_in@Wi + bi)*0.1*ne2  -> out[4]  (new_cell final)
//   R3/E3: C_t = leaky(bn3(new_cell))          -> out[2]
//   P   : p[i] = (LC_t+NE_t+C_t)[i,:] . WP
//   G7  : Pupil = sigmoid(C_t@Wo + bo) * (p + bP)  -> out[3]
// ---------------------------------------------------------------------------

#define B_DIM 65536
#define H_DIM 256
#define BH_ELEMS (B_DIM * H_DIM)      // 16,777,216

#define BM 128
#define BN 128
#define BK 16
#define TM 8
#define TN 8

#define NCHUNK 1024
#define ROWS_PER_CHUNK (B_DIM / NCHUNK)   // 64
#define BN_EPS_F 1e-5f
#define LAMBDA_C 0.1f

// ------------------------------ scratch (global, no allocs) ----------------
__device__ float g_xin[BH_ELEMS];                 // x_input
__device__ float g_raw[BH_ELEMS];                 // LC_raw / NE_raw / ne2 (reused)
__device__ float g_forget[BH_ELEMS];              // forget gate
__device__ float g_p[B_DIM];                      // pupil pre-activation [B]
__device__ float g_part[2 * H_DIM * NCHUNK];      // column partial sums / sumsq
__device__ float g_scale[H_DIM];                  // BN fused scale
__device__ float g_shift[H_DIM];                  // BN fused shift

__device__ __forceinline__ float sigmoidf_(float x) { return 1.0f / (1.0f + expf(-x)); }
__device__ __forceinline__ float leakyf_(float x)   { return x > 0.0f ? x : 0.1f * x; }

// ------------------------------ GEMM core ----------------------------------
// acc += A[rowBase:+128, 0:256] @ W[0:256, colBase:+128]
// A: [*,256] row-major, W: [256,256] row-major. 256 threads, 8x8 per thread.
// Thread (tx,ty): rows rowBase+ty*8+i; cols colBase + {tx*4+q, 64+tx*4+q}.
__device__ __forceinline__ void mm256(const float* __restrict__ A,
                                      const float* __restrict__ W,
                                      int rowBase, int colBase,
                                      float (&acc)[TM][TN],
                                      float* sA, float* sW)
{
    const int tid = threadIdx.x;
    const int tx = tid & 15, ty = tid >> 4;
    for (int kt = 0; kt < 256; kt += BK) {
        // A tile [128 x 16] -> sA transposed as [16][128]
        #pragma unroll
        for (int l = 0; l < 2; ++l) {
            int fi = tid + l * 256;            // 0..511 float4 slots
            int r  = fi >> 2;                  // 0..127
            int c4 = fi & 3;                   // 0..3
            float4 v = *(const float4*)(A + (size_t)(rowBase + r) * H_DIM + kt + c4 * 4);
            sA[(c4 * 4 + 0) * BM + r] = v.x;
            sA[(c4 * 4 + 1) * BM + r] = v.y;
            sA[(c4 * 4 + 2) * BM + r] = v.z;
            sA[(c4 * 4 + 3) * BM + r] = v.w;
        }
        // W tile [16 x 128] -> sW row-major
        #pragma unroll
        for (int l = 0; l < 2; ++l) {
            int fi = tid + l * 256;
            int r  = fi >> 5;                  // 0..15
            int c4 = fi & 31;                  // 0..31
            *(float4*)(sW + r * BN + c4 * 4) =
                *(const float4*)(W + (size_t)(kt + r) * H_DIM + colBase + c4 * 4);
        }
        __syncthreads();
        #pragma unroll
        for (int k = 0; k < BK; ++k) {
            float ra[TM], rb[TN];
            *(float4*)(ra)     = *(const float4*)(sA + k * BM + ty * TM);
            *(float4*)(ra + 4) = *(const float4*)(sA + k * BM + ty * TM + 4);
            *(float4*)(rb)     = *(const float4*)(sW + k * BN + tx * 4);
            *(float4*)(rb + 4) = *(const float4*)(sW + k * BN + 64 + tx * 4);
            #pragma unroll
            for (int i = 0; i < TM; ++i)
                #pragma unroll
                for (int j = 0; j < TN; ++j)
                    acc[i][j] += ra[i] * rb[j];
        }
        __syncthreads();
    }
}

// Column index of acc[i][jj*4+q] relative to colBase:  jj*64 + tx*4 + q
#define EPI_BEGIN()                                                         \
    const int tx = threadIdx.x & 15, ty = threadIdx.x >> 4;                 \
    _Pragma("unroll")                                                       \
    for (int i = 0; i < TM; ++i) {                                          \
        const int row = rowBase + ty * TM + i;                              \
        const size_t ro = (size_t)row * H_DIM;                              \
        _Pragma("unroll")                                                   \
        for (int jj = 0; jj < 2; ++jj) {                                    \
            const int cb = colBase + jj * 64 + tx * 4;                      \
            float t[4];                                                     \
            _Pragma("unroll")                                               \
            for (int q = 0; q < 4; ++q) {                                   \
                const float a = acc[i][jj * 4 + q];                         \
                const int col = cb + q;                                     \
                (void)col;

#define EPI_END(dst)                                                        \
            }                                                               \
            *(float4*)((dst) + ro + cb) = *(float4*)t;                      \
        }                                                                   \
    }

// ------------------------------ GEMM kernels -------------------------------

// G1: x_in = X@Wx+bx (-> g_xin); LC_raw = x_in + prev_LC@Wh + bh (-> g_raw)
__global__ __launch_bounds__(256) void k_gemm_s1(
    const float* __restrict__ X,  const float* __restrict__ Wx, const float* __restrict__ bx,
    const float* __restrict__ pLC, const float* __restrict__ Wh, const float* __restrict__ bh)
{
    __shared__ __align__(16) float sA[BK * BM];
    __shared__ __align__(16) float sW[BK * BN];
    const int rowBase = blockIdx.y * BM, colBase = blockIdx.x * BN;
    float acc[TM][TN] = {};
    mm256(X, Wx, rowBase, colBase, acc, sA, sW);
    {
        EPI_BEGIN()
            t[q] = a + bx[col];
        EPI_END(g_xin)
    }
    mm256(pLC, Wh, rowBase, colBase, acc, sA, sW);
    {
        EPI_BEGIN()
            t[q] = a + bx[col] + bh[col];
        EPI_END(g_raw)
    }
}

// G2: forget = sigmoid(prev_Cortex@Wf + bf) -> g_forget
__global__ __launch_bounds__(256) void k_gemm_forget(
    const float* __restrict__ pC, const float* __restrict__ Wf, const float* __restrict__ bf)
{
    __shared__ __align__(16) float sA[BK * BM];
    __shared__ __align__(16) float sW[BK * BN];
    const int rowBase = blockIdx.y * BM, colBase = blockIdx.x * BN;
    float acc[TM][TN] = {};
    mm256(pC, Wf, rowBase, colBase, acc, sA, sW);
    EPI_BEGIN()
        t[q] = sigmoidf_(a + bf[col]);
    EPI_END(g_forget)
}

// G3/G5: g_raw = A@WLC + bLC   (A = LC_t or NE_t)
__global__ __launch_bounds__(256) void k_gemm_ne(
    const float* __restrict__ Amat, const float* __restrict__ W, const float* __restrict__ bvec)
{
    __shared__ __align__(16) float sA[BK * BM];
    __shared__ __align__(16) float sW[BK * BN];
    const int rowBase = blockIdx.y * BM, colBase = blockIdx.x * BN;
    float acc[TM][TN] = {};
    mm256(Amat, W, rowBase, colBase, acc, sA, sW);
    EPI_BEGIN()
        t[q] = a + bvec[col];
    EPI_END(g_raw)
}

// G4: newcell_partial = x_in@WC + bC + forget*cell  -> NC (d_out region 4)
__global__ __launch_bounds__(256) void k_gemm_cell_a(
    const float* __restrict__ WC, const float* __restrict__ bC,
    const float* __restrict__ cell, float* __restrict__ NC)
{
    __shared__ __align__(16) float sA[BK * BM];
    __shared__ __align__(16) float sW[BK * BN];
    const int rowBase = blockIdx.y * BM, colBase = blockIdx.x * BN;
    float acc[TM][TN] = {};
    mm256(g_xin, WC, rowBase, colBase, acc, sA, sW);
    EPI_BEGIN()
        if (q == 0) {}  // keep structure
        {
            float fg[4], cs[4];
            if (q == 0) {
                *(float4*)fg = *(const float4*)(g_forget + ro + cb);
                *(float4*)cs = *(const float4*)(cell + ro + cb);
                t[0] = a + bC[col] + fg[0] * cs[0];
                t[1] = acc[i][jj * 4 + 1] + bC[cb + 1] + fg[1] * cs[1];
                t[2] = acc[i][jj * 4 + 2] + bC[cb + 2] + fg[2] * cs[2];
                t[3] = acc[i][jj * 4 + 3] + bC[cb + 3] + fg[3] * cs[3];
            }
        }
    EPI_END(NC)
}

// G6: NC += sigmoid(x_in@Wi + bi) * 0.1 * ne2(g_raw)  -> NC final new_cell
__global__ __launch_bounds__(256) void k_gemm_ig(
    const float* __restrict__ Wi, const float* __restrict__ bi, float* __restrict__ NC)
{
    __shared__ __align__(16) float sA[BK * BM];
    __shared__ __align__(16) float sW[BK * BN];
    const int rowBase = blockIdx.y * BM, colBase = blockIdx.x * BN;
    float acc[TM][TN] = {};
    mm256(g_xin, Wi, rowBase, colBase, acc, sA, sW);
    EPI_BEGIN()
        {
            float ne2 = g_raw[ro + col];
            float nc  = NC[ro + col];
            t[q] = nc + sigmoidf_(a + bi[col]) * LAMBDA_C * ne2;
        }
    EPI_END(NC)
}

// G7: Pupil = sigmoid(C_t@Wo + bo) * (g_p[row] + bP[0])
__global__ __launch_bounds__(256) void k_gemm_pupil(
    const float* __restrict__ Ct, const float* __restrict__ Wo, const float* __restrict__ bo,
    const float* __restrict__ bP, float* __restrict__ Pup)
{
    __shared__ __align__(16) float sA[BK * BM];
    __shared__ __align__(16) float sW[BK * BN];
    const int rowBase = blockIdx.y * BM, colBase = blockIdx.x * BN;
    float acc[TM][TN] = {};
    mm256(Ct, Wo, rowBase, colBase, acc, sA, sW);
    const float pb = bP[0];
    EPI_BEGIN()
        {
            float pp = g_p[row] + pb;
            t[q] = sigmoidf_(a + bo[col]) * pp;
        }
    EPI_END(Pup)
}

// ------------------------------ BN reductions ------------------------------

// pass 1: per-(chunk,column) partial sum / sumsq.  x = ext (if use_ext) else g_raw
__global__ void k_colstat1(const float* __restrict__ ext, int use_ext)
{
    const float* x = use_ext ? ext : g_raw;
    const int col = threadIdx.x;      // 0..255
    const int ch  = blockIdx.x;       // 0..NCHUNK-1
    const float* p = x + (size_t)ch * ROWS_PER_CHUNK * H_DIM + col;
    float s = 0.0f, s2 = 0.0f;
    #pragma unroll 8
    for (int r = 0; r < ROWS_PER_CHUNK; ++r) {
        float v = p[(size_t)r * H_DIM];
        s += v; s2 += v * v;
    }
    g_part[col * NCHUNK + ch] = s;
    g_part[H_DIM * NCHUNK + col * NCHUNK + ch] = s2;
}

// pass 2: one block per column -> g_scale/g_shift (fused gamma/beta)
__global__ void k_colstat2(const float* __restrict__ gamma, const float* __restrict__ beta)
{
    const int b = blockIdx.x, t = threadIdx.x;
    float s = 0.0f, s2 = 0.0f;
    #pragma unroll
    for (int q = 0; q < NCHUNK / 256; ++q) {
        int ch = t * (NCHUNK / 256) + q;
        s  += g_part[b * NCHUNK + ch];
        s2 += g_part[H_DIM * NCHUNK + b * NCHUNK + ch];
    }
    __shared__ float rs[256], rq[256];
    rs[t] = s; rq[t] = s2;
    __syncthreads();
    for (int off = 128; off > 0; off >>= 1) {
        if (t < off) { rs[t] += rs[t + off]; rq[t] += rq[t + off]; }
        __syncthreads();
    }
    if (t == 0) {
        float mean = rs[0] * (1.0f / B_DIM);
        float var  = rq[0] * (1.0f / B_DIM) - mean * mean;
        float sc   = gamma[b] * rsqrtf(var + BN_EPS_F);
        g_scale[b] = sc;
        g_shift[b] = beta[b] - mean * sc;
    }
}

// elementwise: out = leaky(in*scale + shift)
__global__ void k_bnleaky(const float* __restrict__ ext, int use_ext, float* __restrict__ out)
{
    const float* in = use_ext ? ext : g_raw;
    size_t i = (size_t)blockIdx.x * blockDim.x + threadIdx.x;  // over BH/4
    int colb = (int)(i & 63) * 4;
    float4 v = ((const float4*)in)[i];
    float t[4] = {v.x, v.y, v.z, v.w};
    float o[4];
    #pragma unroll
    for (int q = 0; q < 4; ++q) {
        float y = t[q] * g_scale[colb + q] + g_shift[colb + q];
        o[q] = leakyf_(y);
    }
    ((float4*)out)[i] = *(float4*)o;
}

// pupil pre: g_p[row] = (LC_t + NE_t + C_t)[row,:] . WP
__global__ void k_pupil(const float* __restrict__ out_base, const float* __restrict__ WP)
{
    const int warp = threadIdx.x >> 5, lane = threadIdx.x & 31;
    const int row = blockIdx.x * 8 + warp;
    const size_t off = (size_t)row * H_DIM;
    const float* LC = out_base;
    const float* NE = out_base + (size_t)BH_ELEMS;
    const float* CT = out_base + 2 * (size_t)BH_ELEMS;
    float s = 0.0f;
    #pragma unroll
    for (int h = 0; h < 2; ++h) {
        int c = lane * 4 + h * 128;
        float4 a = *(const float4*)(LC + off + c);
        float4 b = *(const float4*)(NE + off + c);
        float4 d = *(const float4*)(CT + off + c);
        float4 w = *(const float4*)(WP + c);
        s += (a.x + b.x + d.x) * w.x + (a.y + b.y + d.y) * w.y
           + (a.z + b.z + d.z) * w.z + (a.w + b.w + d.w) * w.w;
    }
    #pragma unroll
    for (int o = 16; o > 0; o >>= 1) s += __shfl_xor_sync(0xffffffffu, s, o);
    if (lane == 0) g_p[row] = s;
}

// ------------------------------ launcher -----------------------------------
extern "C" void kernel_launch(void* const* d_in, const int* in_sizes, int n_in,
                              void* d_out, int out_size)
{
    (void)in_sizes; (void)n_in; (void)out_size;
    const float* X    = (const float*)d_in[0];
    const float* pLC  = (const float*)d_in[1];
    const float* pC   = (const float*)d_in[2];
    const float* cell = (const float*)d_in[3];
    const float* Wx   = (const float*)d_in[4];
    const float* bx   = (const float*)d_in[5];
    const float* Wh   = (const float*)d_in[6];
    const float* bh   = (const float*)d_in[7];
    const float* WLC  = (const float*)d_in[8];
    const float* bLC  = (const float*)d_in[9];
    const float* WC   = (const float*)d_in[10];
    const float* bC   = (const float*)d_in[11];
    const float* WP   = (const float*)d_in[12];
    const float* bP   = (const float*)d_in[13];
    const float* Wf   = (const float*)d_in[14];
    const float* bf   = (const float*)d_in[15];
    const float* Wi   = (const float*)d_in[16];
    const float* bi   = (const float*)d_in[17];
    const float* Wo   = (const float*)d_in[18];
    const float* bo   = (const float*)d_in[19];
    const float* g1   = (const float*)d_in[20];
    const float* be1  = (const float*)d_in[21];
    const float* g2   = (const float*)d_in[22];
    const float* be2  = (const float*)d_in[23];
    const float* g3   = (const float*)d_in[24];
    const float* be3  = (const float*)d_in[25];

    float* out  = (float*)d_out;
    float* LC_t = out;
    float* NE_t = out + (size_t)BH_ELEMS;
    float* C_t  = out + 2 * (size_t)BH_ELEMS;
    float* Pup  = out + 3 * (size_t)BH_ELEMS;
    float* NC   = out + 4 * (size_t)BH_ELEMS;

    dim3 gg(H_DIM / BN, B_DIM / BM);   // (2, 512)
    const int EW_GRID = BH_ELEMS / 4 / 256;  // 16384

    // Stage 1: x_in, LC_raw, forget
    k_gemm_s1<<<gg, 256>>>(X, Wx, bx, pLC, Wh, bh);
    k_gemm_forget<<<gg, 256>>>(pC, Wf, bf);

    // BN1 -> LC_t
    k_colstat1<<<NCHUNK, 256>>>(nullptr, 0);
    k_colstat2<<<H_DIM, 256>>>(g1, be1);
    k_bnleaky<<<EW_GRID, 256>>>(nullptr, 0, LC_t);

    // NE_raw -> BN2 -> NE_t
    k_gemm_ne<<<gg, 256>>>(LC_t, WLC, bLC);
    k_colstat1<<<NCHUNK, 256>>>(nullptr, 0);
    k_colstat2<<<H_DIM, 256>>>(g2, be2);
    k_bnleaky<<<EW_GRID, 256>>>(nullptr, 0, NE_t);

    // new_cell = forget*cell + x_in@WC+bC  + 0.1*ig*(NE_t@WLC+bLC)
    k_gemm_cell_a<<<gg, 256>>>(WC, bC, cell, NC);
    k_gemm_ne<<<gg, 256>>>(NE_t, WLC, bLC);       // ne2 -> g_raw
    k_gemm_ig<<<gg, 256>>>(Wi, bi, NC);

    // BN3 -> C_t
    k_colstat1<<<NCHUNK, 256>>>(NC, 1);
    k_colstat2<<<H_DIM, 256>>>(g3, be3);
    k_bnleaky<<<EW_GRID, 256>>>(NC, 1, C_t);

    // Pupil
    k_pupil<<<B_DIM / 8, 256>>>(out, WP);
    k_gemm_pupil<<<gg, 256>>>(C_t, Wo, bo, bP, Pup);
}

// round 16
// speedup vs baseline: 1.3624x; 1.3578x over previous
#include <cuda_runtime.h>
#include <cuda_bf16.h>
#include <stdint.h>
#include <math.h>

// ===========================================================================
// LCNECortexLSTM -- split-bf16 GEMMs via mma.sync (HMMA tensor path, baseline
// sm_103 PTX -- tcgen05 is NOT available in this toolchain, proven by ptxas).
// C = Ah@Bh + Al@Bh + Ah@Bl with fp32 accumulation. B=65536, D=H=256.
// ===========================================================================

#define B_DIM 65536
#define H_DIM 256
#define BH_ELEMS (B_DIM * H_DIM)
#define NCHUNK 1024
#define ROWS_PER_CHUNK (B_DIM / NCHUNK)
#define BN_EPS_F 1e-5f

// dynamic SMEM layout for the GEMM kernel (bf16 elements, row stride 40)
#define SA_STRIDE 40
#define SB_STRIDE 40
#define SMEM_AH 0u
#define SMEM_AL 5120u
#define SMEM_BH 10240u
#define SMEM_BL 30720u
#define SMEM_BYTES 51200

#define M_XIN   0
#define M_LCRAW 1
#define M_SIG   2
#define M_NE    3
#define M_CELL  4
#define M_IG    5
#define M_PUPIL 6

typedef __nv_bfloat16 bf16;

// ------------------------------ device globals -----------------------------
__device__ bf16 S1h[BH_ELEMS], S1l[BH_ELEMS];
__device__ bf16 S2h[BH_ELEMS], S2l[BH_ELEMS];
__device__ bf16 S3h[BH_ELEMS], S3l[BH_ELEMS];
__device__ bf16 g_Ih[BH_ELEMS], g_Il[BH_ELEMS];
__device__ float g_raw[BH_ELEMS];
__device__ float g_forget[BH_ELEMS];
__device__ float g_p[B_DIM];
__device__ float g_part[2 * H_DIM * NCHUNK];
__device__ float g_scale[H_DIM], g_shift[H_DIM];

__device__ bf16 wWxh[65536], wWxl[65536];
__device__ bf16 wWhh[65536], wWhl[65536];
__device__ bf16 wLCh[65536], wLCl[65536];
__device__ bf16 wWCh[65536], wWCl[65536];
__device__ bf16 wWfh[65536], wWfl[65536];
__device__ bf16 wWih[65536], wWil[65536];
__device__ bf16 wWoh[65536], wWol[65536];

// device-side selectors (plain functions; no static pointer init)
__device__ __forceinline__ bf16* a_hi(int i) {
    if (i == 0) return S1h;
    if (i == 1) return S2h;
    if (i == 2) return S3h;
    return g_Ih;
}
__device__ __forceinline__ bf16* a_lo(int i) {
    if (i == 0) return S1l;
    if (i == 1) return S2l;
    if (i == 2) return S3l;
    return g_Il;
}
__device__ __forceinline__ bf16* w_hi(int i) {
    if (i == 0) return wWxh;
    if (i == 1) return wWhh;
    if (i == 2) return wLCh;
    if (i == 3) return wWCh;
    if (i == 4) return wWfh;
    if (i == 5) return wWih;
    return wWoh;
}
__device__ __forceinline__ bf16* w_lo(int i) {
    if (i == 0) return wWxl;
    if (i == 1) return wWhl;
    if (i == 2) return wLCl;
    if (i == 3) return wWCl;
    if (i == 4) return wWfl;
    if (i == 5) return wWil;
    return wWol;
}

// ------------------------------ helpers ------------------------------------
__device__ __forceinline__ float sigf_(float x) { return 1.0f / (1.0f + expf(-x)); }
__device__ __forceinline__ float leakyf_(float x) { return x > 0.0f ? x : 0.1f * x; }
__device__ __forceinline__ float bf2f_(unsigned short u) {
    bf16 b = *reinterpret_cast<bf16*>(&u);
    return __bfloat162float(b);
}
__device__ __forceinline__ void split1(float x, unsigned short& h, unsigned short& l) {
    bf16 hb = __float2bfloat16(x);
    bf16 lb = __float2bfloat16(x - __bfloat162float(hb));
    h = *reinterpret_cast<unsigned short*>(&hb);
    l = *reinterpret_cast<unsigned short*>(&lb);
}
__device__ __forceinline__ void store_hl4(float x0, float x1, float x2, float x3,
                                          size_t idx, bf16* oh, bf16* ol) {
    ushort4 H, L;
    split1(x0, H.x, L.x);
    split1(x1, H.y, L.y);
    split1(x2, H.z, L.z);
    split1(x3, H.w, L.w);
    *reinterpret_cast<ushort4*>(oh + idx) = H;
    *reinterpret_cast<ushort4*>(ol + idx) = L;
}

// m16n8k16 row.col bf16 -> f32 accumulate (baseline PTX, sm_80+)
__device__ __forceinline__ void mma16816(float* c, const uint32_t* a, const uint32_t* b) {
    asm volatile(
        "mma.sync.aligned.m16n8k16.row.col.f32.bf16.bf16.f32 "
        "{%0,%1,%2,%3}, {%4,%5,%6,%7}, {%8,%9}, {%0,%1,%2,%3};"
        : "+f"(c[0]), "+f"(c[1]), "+f"(c[2]), "+f"(c[3])
        : "r"(a[0]), "r"(a[1]), "r"(a[2]), "r"(a[3]), "r"(b[0]), "r"(b[1]));
}

// ------------------------------ epilogue op (2-wide) ------------------------
__device__ __forceinline__ void epi2(int mode, float x0, float x1, int row, int col,
                                     const float* bias, const float* aux, float* outF) {
    size_t idx = (size_t)row * 256 + col;
    x0 += bias[col];
    x1 += bias[col + 1];
    if (mode == M_XIN) {
        unsigned short h0, l0, h1, l1;
        split1(x0, h0, l0);
        split1(x1, h1, l1);
        ushort2 H, L;
        H.x = h0; H.y = h1;
        L.x = l0; L.y = l1;
        *reinterpret_cast<ushort2*>(g_Ih + idx) = H;
        *reinterpret_cast<ushort2*>(g_Il + idx) = L;
        return;
    } else if (mode == M_LCRAW) {
        ushort2 H = *reinterpret_cast<const ushort2*>(g_Ih + idx);
        ushort2 L = *reinterpret_cast<const ushort2*>(g_Il + idx);
        x0 += bf2f_(H.x) + bf2f_(L.x);
        x1 += bf2f_(H.y) + bf2f_(L.y);
    } else if (mode == M_SIG) {
        x0 = sigf_(x0);
        x1 = sigf_(x1);
    } else if (mode == M_CELL) {
        float2 fg = *reinterpret_cast<const float2*>(g_forget + idx);
        float2 cs = *reinterpret_cast<const float2*>(aux + idx);
        x0 += fg.x * cs.x;
        x1 += fg.y * cs.y;
    } else if (mode == M_IG) {
        float2 ne = *reinterpret_cast<const float2*>(g_raw + idx);
        float2 nc = *reinterpret_cast<const float2*>(outF + idx);
        x0 = nc.x + sigf_(x0) * 0.1f * ne.x;
        x1 = nc.y + sigf_(x1) * 0.1f * ne.y;
    } else if (mode == M_PUPIL) {
        float pp = g_p[row] + aux[0];
        x0 = sigf_(x0) * pp;
        x1 = sigf_(x1) * pp;
    }
    float2 o;
    o.x = x0;
    o.y = x1;
    *reinterpret_cast<float2*>(outF + idx) = o;
}

// ------------------------------ mma.sync GEMM -------------------------------
// CTA: 64 rows x 256 cols. 8 warps, warp tile 32x64.
// K loop: 8 chunks of 32; per chunk stage Ah/Al/Bh/Bl; 3 split products.
__global__ void __launch_bounds__(256)
k_mma(int mode, int ai, int wi, const float* bias, const float* aux,
      float* outExt, int outsel) {
    extern __shared__ __align__(16) char smc[];
    bf16* sAh = reinterpret_cast<bf16*>(smc + SMEM_AH);
    bf16* sAl = reinterpret_cast<bf16*>(smc + SMEM_AL);
    bf16* sBh = reinterpret_cast<bf16*>(smc + SMEM_BH);
    bf16* sBl = reinterpret_cast<bf16*>(smc + SMEM_BL);

    const int tid = threadIdx.x;
    const int w = tid >> 5;
    const int lane = tid & 31;
    const int g = lane >> 2;
    const int qt = lane & 3;
    const int rowBase = blockIdx.x * 64;
    const int wrow = (w & 1) * 32;
    const int wcol = (w >> 1) * 64;

    const bf16* Ah = a_hi(ai);
    const bf16* Al = a_lo(ai);
    const bf16* Bh = w_hi(wi);
    const bf16* Bl = w_lo(wi);
    float* outF = outExt;
    if (outsel == 0) outF = g_raw;
    if (outsel == 1) outF = g_forget;

    float c[2][8][4];
    #pragma unroll
    for (int mt = 0; mt < 2; ++mt)
        #pragma unroll
        for (int nt = 0; nt < 8; ++nt)
            #pragma unroll
            for (int q = 0; q < 4; ++q)
                c[mt][nt][q] = 0.0f;

    for (int k0 = 0; k0 < 256; k0 += 32) {
        // stage A chunks: 64 rows x 32 k; one uint4 (8 bf16) per thread each
        {
            int r = tid >> 2;
            int c8 = tid & 3;
            size_t go = (size_t)(rowBase + r) * 256 + k0 + c8 * 8;
            *reinterpret_cast<uint4*>(sAh + r * SA_STRIDE + c8 * 8) =
                *reinterpret_cast<const uint4*>(Ah + go);
            *reinterpret_cast<uint4*>(sAl + r * SA_STRIDE + c8 * 8) =
                *reinterpret_cast<const uint4*>(Al + go);
        }
        // stage B chunks: 256 rows x 32 k; 4 uint4 per thread each
        #pragma unroll
        for (int i = 0; i < 4; ++i) {
            int u = tid + i * 256;
            int r = u >> 2;
            int c8 = u & 3;
            size_t go = (size_t)r * 256 + k0 + c8 * 8;
            *reinterpret_cast<uint4*>(sBh + r * SB_STRIDE + c8 * 8) =
                *reinterpret_cast<const uint4*>(Bh + go);
            *reinterpret_cast<uint4*>(sBl + r * SB_STRIDE + c8 * 8) =
                *reinterpret_cast<const uint4*>(Bl + go);
        }
        __syncthreads();

        #pragma unroll
        for (int kk = 0; kk < 32; kk += 16) {
            // A fragments for hi and lo splits
            uint32_t fah[2][4], fal[2][4];
            #pragma unroll
            for (int mt = 0; mt < 2; ++mt) {
                int r0 = wrow + mt * 16 + g;
                int kb = kk + qt * 2;
                fah[mt][0] = *reinterpret_cast<const uint32_t*>(sAh + r0 * SA_STRIDE + kb);
                fah[mt][1] = *reinterpret_cast<const uint32_t*>(sAh + (r0 + 8) * SA_STRIDE + kb);
                fah[mt][2] = *reinterpret_cast<const uint32_t*>(sAh + r0 * SA_STRIDE + kb + 8);
                fah[mt][3] = *reinterpret_cast<const uint32_t*>(sAh + (r0 + 8) * SA_STRIDE + kb + 8);
                fal[mt][0] = *reinterpret_cast<const uint32_t*>(sAl + r0 * SA_STRIDE + kb);
                fal[mt][1] = *reinterpret_cast<const uint32_t*>(sAl + (r0 + 8) * SA_STRIDE + kb);
                fal[mt][2] = *reinterpret_cast<const uint32_t*>(sAl + r0 * SA_STRIDE + kb + 8);
                fal[mt][3] = *reinterpret_cast<const uint32_t*>(sAl + (r0 + 8) * SA_STRIDE + kb + 8);
            }
            // B-hi fragments feed both Ah and Al products
            #pragma unroll
            for (int nt = 0; nt < 8; ++nt) {
                int rn = wcol + nt * 8 + g;
                int kb = kk + qt * 2;
                uint32_t fb[2];
                fb[0] = *reinterpret_cast<const uint32_t*>(sBh + rn * SB_STRIDE + kb);
                fb[1] = *reinterpret_cast<const uint32_t*>(sBh + rn * SB_STRIDE + kb + 8);
                mma16816(c[0][nt], fah[0], fb);
                mma16816(c[1][nt], fah[1], fb);
                mma16816(c[0][nt], fal[0], fb);
                mma16816(c[1][nt], fal[1], fb);
            }
            // B-lo fragments feed the Ah product only
            #pragma unroll
            for (int nt = 0; nt < 8; ++nt) {
                int rn = wcol + nt * 8 + g;
                int kb = kk + qt * 2;
                uint32_t fb[2];
                fb[0] = *reinterpret_cast<const uint32_t*>(sBl + rn * SB_STRIDE + kb);
                fb[1] = *reinterpret_cast<const uint32_t*>(sBl + rn * SB_STRIDE + kb + 8);
                mma16816(c[0][nt], fah[0], fb);
                mma16816(c[1][nt], fah[1], fb);
            }
        }
        __syncthreads();
    }

    // epilogue: fragment (c0,c1) -> (row, col..col+1); (c2,c3) -> row+8
    #pragma unroll
    for (int mt = 0; mt < 2; ++mt) {
        #pragma unroll
        for (int nt = 0; nt < 8; ++nt) {
            int r0 = rowBase + wrow + mt * 16 + g;
            int col = wcol + nt * 8 + qt * 2;
            epi2(mode, c[mt][nt][0], c[mt][nt][1], r0, col, bias, aux, outF);
            epi2(mode, c[mt][nt][2], c[mt][nt][3], r0 + 8, col, bias, aux, outF);
        }
    }
}

// ------------------------------ prep kernels -------------------------------
__global__ void k_wsplit(const float* W, int wi) {
    __shared__ float tbuf[32][33];
    bf16* Th = w_hi(wi);
    bf16* Tl = w_lo(wi);
    const int bx = blockIdx.x;
    const int by = blockIdx.y;
    const int x = threadIdx.x;
    const int y = threadIdx.y;
    #pragma unroll
    for (int j = 0; j < 32; j += 8)
        tbuf[y + j][x] = W[(size_t)(by * 32 + y + j) * 256 + bx * 32 + x];
    __syncthreads();
    #pragma unroll
    for (int j = 0; j < 32; j += 8) {
        int n = bx * 32 + y + j;
        int k = by * 32 + x;
        unsigned short h, l;
        split1(tbuf[x][y + j], h, l);
        Th[(size_t)n * 256 + k] = *reinterpret_cast<bf16*>(&h);
        Tl[(size_t)n * 256 + k] = *reinterpret_cast<bf16*>(&l);
    }
}

__global__ void k_asplit(const float* src, int si) {
    bf16* h = a_hi(si);
    bf16* l = a_lo(si);
    size_t i = (size_t)blockIdx.x * 256 + threadIdx.x;
    float4 v = reinterpret_cast<const float4*>(src)[i];
    store_hl4(v.x, v.y, v.z, v.w, i * 4, h, l);
}

// ------------------------------ BN kernels ---------------------------------
__global__ void k_colstat1(const float* ext, int use_ext) {
    const float* x = use_ext ? ext : g_raw;
    const int col = threadIdx.x;
    const int ch = blockIdx.x;
    const float* p = x + (size_t)ch * ROWS_PER_CHUNK * H_DIM + col;
    float s = 0.0f, s2 = 0.0f;
    #pragma unroll 8
    for (int r = 0; r < ROWS_PER_CHUNK; ++r) {
        float v = p[(size_t)r * H_DIM];
        s += v;
        s2 += v * v;
    }
    g_part[col * NCHUNK + ch] = s;
    g_part[H_DIM * NCHUNK + col * NCHUNK + ch] = s2;
}

__global__ void k_colstat2(const float* gamma, const float* beta) {
    const int b = blockIdx.x;
    const int t = threadIdx.x;
    float s = 0.0f, s2 = 0.0f;
    #pragma unroll
    for (int q = 0; q < NCHUNK / 256; ++q) {
        int ch = t * (NCHUNK / 256) + q;
        s  += g_part[b * NCHUNK + ch];
        s2 += g_part[H_DIM * NCHUNK + b * NCHUNK + ch];
    }
    __shared__ float rs[256];
    __shared__ float rq[256];
    rs[t] = s;
    rq[t] = s2;
    __syncthreads();
    for (int off = 128; off > 0; off >>= 1) {
        if (t < off) { rs[t] += rs[t + off]; rq[t] += rq[t + off]; }
        __syncthreads();
    }
    if (t == 0) {
        float mean = rs[0] * (1.0f / B_DIM);
        float var  = rq[0] * (1.0f / B_DIM) - mean * mean;
        float sc   = gamma[b] * rsqrtf(var + BN_EPS_F);
        g_scale[b] = sc;
        g_shift[b] = beta[b] - mean * sc;
    }
}

__global__ void k_bnleaky(const float* ext, int use_ext, float* out, int si) {
    const float* in = use_ext ? ext : g_raw;
    bf16* oh = a_hi(si);
    bf16* ol = a_lo(si);
    size_t i = (size_t)blockIdx.x * 256 + threadIdx.x;
    int colb = (int)(i & 63) * 4;
    float4 v = reinterpret_cast<const float4*>(in)[i];
    float o0 = leakyf_(v.x * g_scale[colb + 0] + g_shift[colb + 0]);
    float o1 = leakyf_(v.y * g_scale[colb + 1] + g_shift[colb + 1]);
    float o2 = leakyf_(v.z * g_scale[colb + 2] + g_shift[colb + 2]);
    float o3 = leakyf_(v.w * g_scale[colb + 3] + g_shift[colb + 3]);
    reinterpret_cast<float4*>(out)[i] = make_float4(o0, o1, o2, o3);
    store_hl4(o0, o1, o2, o3, i * 4, oh, ol);
}

__global__ void k_pupil(const float* out_base, const float* WP) {
    const int warp = threadIdx.x >> 5;
    const int lane = threadIdx.x & 31;
    const int row = blockIdx.x * 8 + warp;
    const size_t off = (size_t)row * H_DIM;
    const float* LC = out_base;
    const float* NE = out_base + (size_t)BH_ELEMS;
    const float* CT = out_base + 2 * (size_t)BH_ELEMS;
    float s = 0.0f;
    #pragma unroll
    for (int h = 0; h < 2; ++h) {
        int c = lane * 4 + h * 128;
        float4 a = *reinterpret_cast<const float4*>(LC + off + c);
        float4 b = *reinterpret_cast<const float4*>(NE + off + c);
        float4 d = *reinterpret_cast<const float4*>(CT + off + c);
        float4 w = *reinterpret_cast<const float4*>(WP + c);
        s += (a.x + b.x + d.x) * w.x + (a.y + b.y + d.y) * w.y
           + (a.z + b.z + d.z) * w.z + (a.w + b.w + d.w) * w.w;
    }
    #pragma unroll
    for (int o = 16; o > 0; o >>= 1) s += __shfl_xor_sync(0xffffffffu, s, o);
    if (lane == 0) g_p[row] = s;
}

// ------------------------------ host driver --------------------------------
static void run_all(void* const* d_in, void* d_out) {
    const float* X    = (const float*)d_in[0];
    const float* pLC  = (const float*)d_in[1];
    const float* pC   = (const float*)d_in[2];
    const float* cell = (const float*)d_in[3];
    const float* Wx   = (const float*)d_in[4];
    const float* bx   = (const float*)d_in[5];
    const float* Wh   = (const float*)d_in[6];
    const float* bh   = (const float*)d_in[7];
    const float* WLC  = (const float*)d_in[8];
    const float* bLC  = (const float*)d_in[9];
    const float* WC   = (const float*)d_in[10];
    const float* bC   = (const float*)d_in[11];
    const float* WP   = (const float*)d_in[12];
    const float* bP   = (const float*)d_in[13];
    const float* Wf   = (const float*)d_in[14];
    const float* bfv  = (const float*)d_in[15];
    const float* Wi   = (const float*)d_in[16];
    const float* bi   = (const float*)d_in[17];
    const float* Wo   = (const float*)d_in[18];
    const float* bo   = (const float*)d_in[19];
    const float* g1   = (const float*)d_in[20];
    const float* be1  = (const float*)d_in[21];
    const float* g2   = (const float*)d_in[22];
    const float* be2  = (const float*)d_in[23];
    const float* g3   = (const float*)d_in[24];
    const float* be3  = (const float*)d_in[25];

    float* out  = (float*)d_out;
    float* LC_t = out;
    float* NE_t = out + (size_t)BH_ELEMS;
    float* C_t  = out + 2 * (size_t)BH_ELEMS;
    float* Pup  = out + 3 * (size_t)BH_ELEMS;
    float* NC   = out + 4 * (size_t)BH_ELEMS;

    cudaFuncSetAttribute((const void*)k_mma,
                         cudaFuncAttributeMaxDynamicSharedMemorySize, SMEM_BYTES);

    dim3 wb(32, 8);
    dim3 wg(8, 8);
    const int EW = BH_ELEMS / 4 / 256;
    const int GG = B_DIM / 64;   // 1024 CTAs per GEMM

    // weight transpose+split: 0=Wx 1=Wh 2=WLC 3=WC 4=Wf 5=Wi 6=Wo
    k_wsplit<<<wg, wb>>>(Wx,  0);
    k_wsplit<<<wg, wb>>>(Wh,  1);
    k_wsplit<<<wg, wb>>>(WLC, 2);
    k_wsplit<<<wg, wb>>>(WC,  3);
    k_wsplit<<<wg, wb>>>(Wf,  4);
    k_wsplit<<<wg, wb>>>(Wi,  5);
    k_wsplit<<<wg, wb>>>(Wo,  6);
    // activation splits: 0=S1(X) 1=S2(pLC) 2=S3(pC)
    k_asplit<<<EW, 256>>>(X,   0);
    k_asplit<<<EW, 256>>>(pLC, 1);
    k_asplit<<<EW, 256>>>(pC,  2);

    // x_in = X@Wx+bx -> g_Ih/g_Il only
    k_mma<<<GG, 256, SMEM_BYTES>>>(M_XIN,   0, 0, bx, (const float*)0, (float*)0, 0);
    // LC_raw = x_in + pLC@Wh + bh -> g_raw
    k_mma<<<GG, 256, SMEM_BYTES>>>(M_LCRAW, 1, 1, bh, (const float*)0, (float*)0, 0);
    // forget = sigmoid(pC@Wf + bfv) -> g_forget
    k_mma<<<GG, 256, SMEM_BYTES>>>(M_SIG,   2, 4, bfv, (const float*)0, (float*)0, 1);

    // BN1 -> LC_t (+ splits into S1)
    k_colstat1<<<NCHUNK, 256>>>((const float*)0, 0);
    k_colstat2<<<H_DIM, 256>>>(g1, be1);
    k_bnleaky<<<EW, 256>>>((const float*)0, 0, LC_t, 0);

    // NE_raw = LC_t@WLC+bLC -> g_raw ; BN2 -> NE_t (+ splits into S2)
    k_mma<<<GG, 256, SMEM_BYTES>>>(M_NE, 0, 2, bLC, (const float*)0, (float*)0, 0);
    k_colstat1<<<NCHUNK, 256>>>((const float*)0, 0);
    k_colstat2<<<H_DIM, 256>>>(g2, be2);
    k_bnleaky<<<EW, 256>>>((const float*)0, 0, NE_t, 1);

    // new_cell = x_in@WC+bC + forget*cell + sigmoid(x_in@Wi+bi)*0.1*(NE_t@WLC+bLC)
    k_mma<<<GG, 256, SMEM_BYTES>>>(M_CELL, 3, 3, bC, cell, NC, -1);
    k_mma<<<GG, 256, SMEM_BYTES>>>(M_NE,   1, 2, bLC, (const float*)0, (float*)0, 0);
    k_mma<<<GG, 256, SMEM_BYTES>>>(M_IG,   3, 5, bi, (const float*)0, NC, -1);

    // BN3 -> C_t (+ splits into S3)
    k_colstat1<<<NCHUNK, 256>>>(NC, 1);
    k_colstat2<<<H_DIM, 256>>>(g3, be3);
    k_bnleaky<<<EW, 256>>>(NC, 1, C_t, 2);

    // Pupil
    k_pupil<<<B_DIM / 8, 256>>>(out, WP);
    k_mma<<<GG, 256, SMEM_BYTES>>>(M_PUPIL, 2, 6, bo, bP, Pup, -1);
}

extern "C" void kernel_launch(void* const* d_in, const int* in_sizes, int n_in,
                              void* d_out, int out_size) {
    (void)in_sizes;
    (void)n_in;
    (void)out_size;
    run_all(d_in, d_out);
}